// round 13
// baseline (speedup 1.0000x reference)
#include <cuda_runtime.h>
#include <cuda_fp16.h>
#include <cstdint>
#include <math.h>

// ---------------------------------------------------------------------------
// Problem constants
// ---------------------------------------------------------------------------
#define T_TOKENS 16384
#define H_DIM    2048
#define N_EXP    64
#define TOPK     8
#define KC       64                  // fp32 k-elements per chunk
#define NCHUNK   (H_DIM / KC)        // 32
#define BM       64                  // tokens per CTA (occupancy 2)
#define GAP_THR  3.0e-5f             // marginal-row flag threshold (abs logit)

// SMEM: double-buffered fp16 tiles, 128 B per row (64 halves), swizzled.
//   per buffer: A_hi 8K | A_lo 8K | B_hi 8K | B_lo 8K = 32 KB
#define BUFSZ    32768
#define AHI_OFF(b)  ((b) * BUFSZ + 0)
#define ALO_OFF(b)  ((b) * BUFSZ + 8192)
#define BHI_OFF(b)  ((b) * BUFSZ + 16384)
#define BLO_OFF(b)  ((b) * BUFSZ + 24576)
#define SMEM_TOTAL  (2 * BUFSZ)      // 65536; epilogue reuses [0,17408) as f32

// 16-byte-granule XOR swizzle within a 128-byte row
#define SWG(row, g) ((g) ^ ((row) & 7))

// ---------------------------------------------------------------------------
// Repair kernel sizing (v3: 8 rows/group, 3-deep cp.async pipeline)
// ---------------------------------------------------------------------------
#define RGRID     32
#define RTHREADS  128
#define RROWS     8
#define SW_STR    132                              // padded floats per W row
#define RSM_SWBUF (64 * SW_STR)                    // 8448 floats per W buffer
#define RSM_SA    (3 * RSM_SWBUF)                  // 25344: A bufs after 3 W bufs
#define RSM_SLOG  (RSM_SA + 3 * RROWS * 128)       // 28416
#define RSM_ROWS  (RSM_SLOG + RROWS * N_EXP)       // 28928
#define REPAIR_SMEM ((RSM_ROWS + RROWS) * 4)       // 115744 bytes

// Compacted list of marginal rows needing exact serial-fp32 recompute.
// Zero-initialized at module load; repair kernel resets counters at exit so
// the zero-at-entry invariant holds across graph replays.
__device__ int g_count;
__device__ int g_done;
__device__ int g_list[T_TOKENS];

static __device__ __forceinline__ uint32_t smem_u32(const void* p) {
    uint32_t a;
    asm("{ .reg .u64 t; cvta.to.shared.u64 t, %1; cvt.u32.u64 %0, t; }"
        : "=r"(a) : "l"(p));
    return a;
}

static __device__ __forceinline__ void ldsm4(uint32_t r[4], uint32_t addr) {
    asm volatile("ldmatrix.sync.aligned.m8n8.x4.shared.b16 {%0,%1,%2,%3}, [%4];"
                 : "=r"(r[0]), "=r"(r[1]), "=r"(r[2]), "=r"(r[3]) : "r"(addr));
}

static __device__ __forceinline__ void mma16816(
    float c[4], const uint32_t a[4], uint32_t b0, uint32_t b1)
{
    asm volatile(
        "mma.sync.aligned.m16n8k16.row.col.f32.f16.f16.f32 "
        "{%0,%1,%2,%3}, {%4,%5,%6,%7}, {%8,%9}, {%0,%1,%2,%3};"
        : "+f"(c[0]), "+f"(c[1]), "+f"(c[2]), "+f"(c[3])
        : "r"(a[0]), "r"(a[1]), "r"(a[2]), "r"(a[3]), "r"(b0), "r"(b1));
}

static __device__ __forceinline__ void cpa16(uint32_t dst, const void* src) {
    asm volatile("cp.async.ca.shared.global [%0], [%1], 16;"
                 :: "r"(dst), "l"(src) : "memory");
}
#define CP_COMMIT() asm volatile("cp.async.commit_group;" ::: "memory")
#define CP_WAIT(n)  asm volatile("cp.async.wait_group %0;" :: "n"(n) : "memory")

// Split 8 fp32 into fp16 hi (16 B) and fp16 lo (16 B).
static __device__ __forceinline__ void cvt8(
    float4 p, float4 q, uint4& hi, uint4& lo)
{
    __half2 h0 = __floats2half2_rn(p.x, p.y);
    __half2 h1 = __floats2half2_rn(p.z, p.w);
    __half2 h2 = __floats2half2_rn(q.x, q.y);
    __half2 h3 = __floats2half2_rn(q.z, q.w);
    float2 f0 = __half22float2(h0), f1 = __half22float2(h1);
    float2 f2 = __half22float2(h2), f3 = __half22float2(h3);
    __half2 l0 = __floats2half2_rn(p.x - f0.x, p.y - f0.y);
    __half2 l1 = __floats2half2_rn(p.z - f1.x, p.w - f1.y);
    __half2 l2 = __floats2half2_rn(q.x - f2.x, q.y - f2.y);
    __half2 l3 = __floats2half2_rn(q.z - f3.x, q.w - f3.y);
    hi.x = *(uint32_t*)&h0; hi.y = *(uint32_t*)&h1;
    hi.z = *(uint32_t*)&h2; hi.w = *(uint32_t*)&h3;
    lo.x = *(uint32_t*)&l0; lo.y = *(uint32_t*)&l1;
    lo.z = *(uint32_t*)&l2; lo.w = *(uint32_t*)&l3;
}

// Shared top-8 + renormalized softmax writer (ties -> lower index).
static __device__ __forceinline__ void topk_and_write(
    const float* v_in, int row, float* vals, float* inds)
{
    float v[N_EXP];
#pragma unroll
    for (int j = 0; j < N_EXP; j++) v[j] = v_in[j];

    float tv[TOPK]; int ti[TOPK];
#pragma unroll
    for (int it = 0; it < TOPK; it++) {
        float bv = -INFINITY; int bi = 0;
#pragma unroll
        for (int j = 0; j < N_EXP; j++)
            if (v[j] > bv) { bv = v[j]; bi = j; }
        tv[it] = bv; ti[it] = bi;
        v[bi] = -INFINITY;
    }

    const float m = tv[0];
    float e[TOPK], s = 0.0f;
#pragma unroll
    for (int i = 0; i < TOPK; i++) { e[i] = expf(tv[i] - m); s += e[i]; }
    const float inv = 1.0f / s;

    *(float4*)(vals + (size_t)row * TOPK) =
        make_float4(e[0]*inv, e[1]*inv, e[2]*inv, e[3]*inv);
    *(float4*)(vals + (size_t)row * TOPK + 4) =
        make_float4(e[4]*inv, e[5]*inv, e[6]*inv, e[7]*inv);
    *(float4*)(inds + (size_t)row * TOPK) =
        make_float4((float)ti[0], (float)ti[1], (float)ti[2], (float)ti[3]);
    *(float4*)(inds + (size_t)row * TOPK + 4) =
        make_float4((float)ti[4], (float)ti[5], (float)ti[6], (float)ti[7]);
}

// ---------------------------------------------------------------------------
// Fused kernel: logits = A @ W^T via HMMA fp16 split (dual accumulators).
// BM=64: warps split M(4) x N(2); occupancy 2 CTAs/SM. Each output element
// is accumulated by one warp over the identical k-order as before ->
// bitwise-identical logits.
// ---------------------------------------------------------------------------
__global__ void __launch_bounds__(256, 2)
router_fused_kernel(const float* __restrict__ A,   // [T, H]
                    const float* __restrict__ W,   // [E, H]
                    float* __restrict__ logits,    // [T, E]
                    float* __restrict__ vals,      // [T, 8]
                    float* __restrict__ inds)      // [T, 8]
{
    extern __shared__ char smem[];
    const uint32_t sb = smem_u32(smem);
    const int tid  = threadIdx.x;
    const int wid  = tid >> 5;
    const int lane = tid & 31;
    const int blockRow = blockIdx.x * BM;
    const int mrow  = (wid & 3) * 16;     // warp's m16 slice (rows 0..63)
    const int nbase = (wid >> 2) * 32;    // warp's n32 half

    float acc[4][4];     // hi*hi
    float acc2[4][4];    // hi*lo + lo*hi
#pragma unroll
    for (int t = 0; t < 4; t++)
#pragma unroll
        for (int j = 0; j < 4; j++) { acc[t][j] = 0.0f; acc2[t][j] = 0.0f; }

    const float* Abase = A + (size_t)blockRow * H_DIM;

    // Cooperative loads: 64 rows x 8 slots (8 floats each) = 512 slots / 256 thr
    const int ldRow[2] = { (tid + 0) >> 3, (tid + 256) >> 3 };
    const int ldG = tid & 7;

    float4 pa[2][2], pw[2][2];

    // ---- prologue: LDG chunk 0, convert+store into buffer 0
#pragma unroll
    for (int t = 0; t < 2; t++) {
        const float* p = Abase + (size_t)ldRow[t] * H_DIM + ldG * 8;
        pa[t][0] = *(const float4*)p;
        pa[t][1] = *(const float4*)(p + 4);
        const float* q = W + (size_t)ldRow[t] * H_DIM + ldG * 8;
        pw[t][0] = *(const float4*)q;
        pw[t][1] = *(const float4*)(q + 4);
    }
#pragma unroll
    for (int t = 0; t < 2; t++) {
        uint4 hi, lo;
        int off = ldRow[t] * 128 + SWG(ldRow[t], ldG) * 16;
        cvt8(pa[t][0], pa[t][1], hi, lo);
        *(uint4*)(smem + AHI_OFF(0) + off) = hi;
        *(uint4*)(smem + ALO_OFF(0) + off) = lo;
        cvt8(pw[t][0], pw[t][1], hi, lo);
        *(uint4*)(smem + BHI_OFF(0) + off) = hi;
        *(uint4*)(smem + BLO_OFF(0) + off) = lo;
    }

    const int lj  = lane >> 3;
    const int lrr = lane & 7;
    const int jr  = (lj & 1) * 8 + lrr;
    const int jg  = lj >> 1;

    for (int c = 0; c < NCHUNK; c++) {
        const int buf = c & 1;

        // ---- issue next chunk's global loads (consumed after MMA)
        if (c + 1 < NCHUNK) {
            const float* Ab = Abase + (c + 1) * KC;
            const float* Wb = W + (c + 1) * KC;
#pragma unroll
            for (int t = 0; t < 2; t++) {
                const float* p = Ab + (size_t)ldRow[t] * H_DIM + ldG * 8;
                pa[t][0] = *(const float4*)p;
                pa[t][1] = *(const float4*)(p + 4);
                const float* q = Wb + (size_t)ldRow[t] * H_DIM + ldG * 8;
                pw[t][0] = *(const float4*)q;
                pw[t][1] = *(const float4*)(q + 4);
            }
        }

        __syncthreads();   // all warps' stores into buf are complete

        // ---- MMA over buf: 4 k16-steps
#pragma unroll
        for (int ks = 0; ks < 4; ks++) {
            const int gk = ks * 2;

            uint32_t ah[4], al[4];
            {
                int arow = mrow + jr;
                int ag   = gk + jg;
                uint32_t off = arow * 128 + SWG(arow, ag) * 16;
                ldsm4(ah, sb + AHI_OFF(buf) + off);
                ldsm4(al, sb + ALO_OFF(buf) + off);
            }

            uint32_t bh[4][2], bl[4][2];
#pragma unroll
            for (int p = 0; p < 2; p++) {
                int brow = nbase + p * 16 + jr;
                int bg   = gk + jg;
                uint32_t off = brow * 128 + SWG(brow, bg) * 16;
                uint32_t r[4];
                ldsm4(r, sb + BHI_OFF(buf) + off);
                bh[2*p][0] = r[0]; bh[2*p][1] = r[2];
                bh[2*p+1][0] = r[1]; bh[2*p+1][1] = r[3];
                ldsm4(r, sb + BLO_OFF(buf) + off);
                bl[2*p][0] = r[0]; bl[2*p][1] = r[2];
                bl[2*p+1][0] = r[1]; bl[2*p+1][1] = r[3];
            }

#pragma unroll
            for (int t = 0; t < 4; t++) {
                mma16816(acc[t],  ah, bh[t][0], bh[t][1]);   // hi*hi -> acc
                mma16816(acc2[t], ah, bl[t][0], bl[t][1]);   // hi*lo -> acc2
                mma16816(acc2[t], al, bh[t][0], bh[t][1]);   // lo*hi -> acc2
            }
        }

        // ---- convert + store next chunk into the other buffer
        if (c + 1 < NCHUNK) {
            const int nbuf = buf ^ 1;
#pragma unroll
            for (int t = 0; t < 2; t++) {
                uint4 hi, lo;
                int off = ldRow[t] * 128 + SWG(ldRow[t], ldG) * 16;
                cvt8(pa[t][0], pa[t][1], hi, lo);
                *(uint4*)(smem + AHI_OFF(nbuf) + off) = hi;
                *(uint4*)(smem + ALO_OFF(nbuf) + off) = lo;
                cvt8(pw[t][0], pw[t][1], hi, lo);
                *(uint4*)(smem + BHI_OFF(nbuf) + off) = hi;
                *(uint4*)(smem + BLO_OFF(nbuf) + off) = lo;
            }
        }
    }

    // Fold the small-term accumulator in once.
#pragma unroll
    for (int t = 0; t < 4; t++)
#pragma unroll
        for (int j = 0; j < 4; j++) acc[t][j] += acc2[t][j];

    __syncthreads();   // all warps done with the final MMA buffer

    // ---------------- Epilogue ----------------
    float* lsm = (float*)smem;   // [64][68] f32 (17408 B)
    {
        const int group = lane >> 2, tig = lane & 3;
#pragma unroll
        for (int t = 0; t < 4; t++) {
            int col = nbase + t * 8 + 2 * tig;
            *(float2*)&lsm[(mrow + group)     * 68 + col] =
                make_float2(acc[t][0], acc[t][1]);
            *(float2*)&lsm[(mrow + group + 8) * 68 + col] =
                make_float2(acc[t][2], acc[t][3]);
        }
    }
    __syncthreads();

    // Coalesced logits store: 64 rows x 16 float4 = 1024 / 256 thr = 4 each
#pragma unroll
    for (int t = 0; t < 4; t++) {
        int i = tid + t * 256;
        int row = i >> 4, q = i & 15;
        float4 v = *(float4*)&lsm[row * 68 + q * 4];
        *(float4*)&logits[(size_t)(blockRow + row) * N_EXP + q * 4] = v;
    }

    // Top-8 + renorm softmax + marginal-row flag: threads 0..63, one row each
    if (tid < BM) {
        const int row = blockRow + tid;
        float v[N_EXP];
#pragma unroll
        for (int j = 0; j < N_EXP; j++) v[j] = lsm[tid * 68 + j];

        float tv[TOPK + 1]; int ti[TOPK];
#pragma unroll
        for (int it = 0; it < TOPK; it++) {
            float bv = -INFINITY; int bi = 0;
#pragma unroll
            for (int j = 0; j < N_EXP; j++)
                if (v[j] > bv) { bv = v[j]; bi = j; }
            tv[it] = bv; ti[it] = bi;
            v[bi] = -INFINITY;
        }
        {
            float bv = -INFINITY;
#pragma unroll
            for (int j = 0; j < N_EXP; j++) bv = fmaxf(bv, v[j]);
            tv[TOPK] = bv;
        }

        float min_gap = INFINITY;
#pragma unroll
        for (int i = 0; i < TOPK; i++) min_gap = fminf(min_gap, tv[i] - tv[i + 1]);
        if (min_gap < GAP_THR) {
            int idx = atomicAdd(&g_count, 1);
            g_list[idx] = row;
        }

        const float m = tv[0];
        float e[TOPK], s = 0.0f;
#pragma unroll
        for (int i = 0; i < TOPK; i++) { e[i] = expf(tv[i] - m); s += e[i]; }
        const float inv = 1.0f / s;

        *(float4*)(vals + (size_t)row * TOPK) =
            make_float4(e[0]*inv, e[1]*inv, e[2]*inv, e[3]*inv);
        *(float4*)(vals + (size_t)row * TOPK + 4) =
            make_float4(e[4]*inv, e[5]*inv, e[6]*inv, e[7]*inv);
        *(float4*)(inds + (size_t)row * TOPK) =
            make_float4((float)ti[0], (float)ti[1], (float)ti[2], (float)ti[3]);
        *(float4*)(inds + (size_t)row * TOPK + 4) =
            make_float4((float)ti[4], (float)ti[5], (float)ti[6], (float)ti[7]);
    }
}

// ---------------------------------------------------------------------------
// Repair kernel v3: serial-in-k fp32 recompute of marginal rows.
// 8 rows per group; 128 threads = (expert e, row-quad pr); 4 chains/thread.
// 3-deep cp.async pipeline, 1 sync per chunk. k-order 0..2047 strictly
// serial per chain -> bitwise-stable results.
// ---------------------------------------------------------------------------
__global__ void __launch_bounds__(RTHREADS)
router_repair_kernel(const float* __restrict__ A,
                     const float* __restrict__ W,
                     float* __restrict__ logits,
                     float* __restrict__ vals,
                     float* __restrict__ inds)
{
    extern __shared__ float rs[];
    float* slog   = rs + RSM_SLOG;        // [8][64]
    int*   rows_s = (int*)(rs + RSM_ROWS);

    const uint32_t sbase = smem_u32(rs);
    const int tid = threadIdx.x;
    const int e   = tid & 63;             // expert
    const int pr  = tid >> 6;             // row-quad: rows 4pr .. 4pr+3

    const int count = g_count;
    const int ngroups = (count + RROWS - 1) / RROWS;

    // prefetch chunk c into buffer b
#define RP_PREFETCH(c, b) do {                                               \
        const float* Wc = W + (c) * 128;                                     \
        uint32_t swb = sbase + (b) * (RSM_SWBUF * 4);                        \
        _Pragma("unroll")                                                    \
        for (int j = 0; j < 16; j++) {                                       \
            int i = tid + RTHREADS * j;                                      \
            int row = i >> 5, q = i & 31;                                    \
            cpa16(swb + (row * SW_STR + q * 4) * 4,                          \
                  Wc + (size_t)row * H_DIM + q * 4);                         \
        }                                                                    \
        _Pragma("unroll")                                                    \
        for (int j = 0; j < 2; j++) {                                        \
            int i = tid + RTHREADS * j;                                      \
            int rr = i >> 5, q = i & 31;                                     \
            int row = rows_s[rr]; if (row < 0) row = 0;                      \
            uint32_t sab = sbase + (RSM_SA + (b) * (RROWS * 128)             \
                                    + rr * 128 + q * 4) * 4;                 \
            cpa16(sab, A + (size_t)row * H_DIM + (c) * 128 + q * 4);         \
        }                                                                    \
        CP_COMMIT();                                                         \
    } while (0)

    for (int g = blockIdx.x; g < ngroups; g += gridDim.x) {
        __syncthreads();                  // protect rows_s/slog reuse
        if (tid < RROWS) {
            int i = g * RROWS + tid;
            rows_s[tid] = (i < count) ? g_list[i] : -1;
        }
        __syncthreads();

        RP_PREFETCH(0, 0);
        RP_PREFETCH(1, 1);

        float acc0 = 0.0f, acc1 = 0.0f, acc2 = 0.0f, acc3 = 0.0f;

        for (int c = 0; c < 16; c++) {
            const int buf = c % 3;
            if (c < 15) { CP_WAIT(1); }   // chunk c complete (c+1 may fly)
            else        { CP_WAIT(0); }
            __syncthreads();              // chunk c visible; buf (c+2)%3 free
            if (c + 2 < 16) RP_PREFETCH(c + 2, (c + 2) % 3);

            const float* swr = rs + buf * RSM_SWBUF + e * SW_STR;
            const float* sa  = rs + RSM_SA + buf * (RROWS * 128) + (pr * 4) * 128;

#pragma unroll
            for (int k4 = 0; k4 < 32; k4++) {
                float4 w4 = *(const float4*)(swr + k4 * 4);
                float4 a0 = *(const float4*)(sa + 0 * 128 + k4 * 4);
                float4 a1 = *(const float4*)(sa + 1 * 128 + k4 * 4);
                float4 a2 = *(const float4*)(sa + 2 * 128 + k4 * 4);
                float4 a3 = *(const float4*)(sa + 3 * 128 + k4 * 4);
                acc0 = fmaf(a0.x, w4.x, acc0); acc0 = fmaf(a0.y, w4.y, acc0);
                acc0 = fmaf(a0.z, w4.z, acc0); acc0 = fmaf(a0.w, w4.w, acc0);
                acc1 = fmaf(a1.x, w4.x, acc1); acc1 = fmaf(a1.y, w4.y, acc1);
                acc1 = fmaf(a1.z, w4.z, acc1); acc1 = fmaf(a1.w, w4.w, acc1);
                acc2 = fmaf(a2.x, w4.x, acc2); acc2 = fmaf(a2.y, w4.y, acc2);
                acc2 = fmaf(a2.z, w4.z, acc2); acc2 = fmaf(a2.w, w4.w, acc2);
                acc3 = fmaf(a3.x, w4.x, acc3); acc3 = fmaf(a3.y, w4.y, acc3);
                acc3 = fmaf(a3.z, w4.z, acc3); acc3 = fmaf(a3.w, w4.w, acc3);
            }
        }

        slog[(pr * 4 + 0) * N_EXP + e] = acc0;
        slog[(pr * 4 + 1) * N_EXP + e] = acc1;
        slog[(pr * 4 + 2) * N_EXP + e] = acc2;
        slog[(pr * 4 + 3) * N_EXP + e] = acc3;
        {
            float av[4] = {acc0, acc1, acc2, acc3};
#pragma unroll
            for (int r = 0; r < 4; r++) {
                int row = rows_s[pr * 4 + r];
                if (row >= 0) logits[(size_t)row * N_EXP + e] = av[r];
            }
        }
        __syncthreads();

        if (tid < RROWS && rows_s[tid] >= 0)
            topk_and_write(slog + tid * N_EXP, rows_s[tid], vals, inds);
    }
#undef RP_PREFETCH

    // Reset counters for the next replay. Every block read g_count before
    // incrementing g_done, so the last-arriving block can safely zero both.
    if (tid == 0) {
        int old = atomicAdd(&g_done, 1);
        if (old == (int)gridDim.x - 1) {
            g_count = 0;
            g_done  = 0;
        }
    }
}

// ---------------------------------------------------------------------------
// Launch
// ---------------------------------------------------------------------------
extern "C" void kernel_launch(void* const* d_in, const int* in_sizes, int n_in,
                              void* d_out, int out_size)
{
    const float* hidden = (const float*)d_in[0];   // [16384, 2048]
    const float* weight = (const float*)d_in[1];   // [64, 2048]
    float* out = (float*)d_out;

    float* logits = out;                                 // 16384*64
    float* vals   = out + (size_t)T_TOKENS * N_EXP;      // 16384*8
    float* inds   = vals + (size_t)T_TOKENS * TOPK;      // 16384*8

    cudaFuncSetAttribute(router_fused_kernel,
                         cudaFuncAttributeMaxDynamicSharedMemorySize, SMEM_TOTAL);
    router_fused_kernel<<<T_TOKENS / BM, 256, SMEM_TOTAL>>>(
        hidden, weight, logits, vals, inds);

    cudaFuncSetAttribute(router_repair_kernel,
                         cudaFuncAttributeMaxDynamicSharedMemorySize, REPAIR_SMEM);
    router_repair_kernel<<<RGRID, RTHREADS, REPAIR_SMEM>>>(
        hidden, weight, logits, vals, inds);
}

// round 14
// speedup vs baseline: 1.0418x; 1.0418x over previous
#include <cuda_runtime.h>
#include <cuda_fp16.h>
#include <cstdint>
#include <math.h>

// ---------------------------------------------------------------------------
// Problem constants
// ---------------------------------------------------------------------------
#define T_TOKENS 16384
#define H_DIM    2048
#define N_EXP    64
#define TOPK     8
#define KC       64                  // fp32 k-elements per chunk
#define NCHUNK   (H_DIM / KC)        // 32
#define BM       128                 // tokens per CTA
#define GAP_THR  3.0e-5f             // marginal-row flag threshold (abs logit)

// SMEM: double-buffered fp16 tiles, 128 B per row (64 halves), swizzled.
//   per buffer: A_hi 16K | A_lo 16K | B_hi 8K | B_lo 8K = 48 KB
#define BUFSZ    49152
#define AHI_OFF(b)  ((b) * BUFSZ + 0)
#define ALO_OFF(b)  ((b) * BUFSZ + 16384)
#define BHI_OFF(b)  ((b) * BUFSZ + 32768)
#define BLO_OFF(b)  ((b) * BUFSZ + 40960)
#define SMEM_TOTAL  (2 * BUFSZ)      // 98304; epilogue reuses [0,34816) as f32

// 16-byte-granule XOR swizzle within a 128-byte row
#define SWG(row, g) ((g) ^ ((row) & 7))

// ---------------------------------------------------------------------------
// Repair kernel sizing (v4: 4 rows/group, 256 threads, 1 chain/thread,
// 3-deep cp.async pipeline)
// ---------------------------------------------------------------------------
#define RGRID     64
#define RTHREADS  256
#define RROWS     4
#define SW_STR    132                              // padded floats per W row
#define RSM_SWBUF (64 * SW_STR)                    // 8448 floats per W buffer
#define RSM_SA    (3 * RSM_SWBUF)                  // A bufs after 3 W bufs
#define RSM_SLOG  (RSM_SA + 3 * RROWS * 128)       // slog after 3 A bufs
#define RSM_ROWS  (RSM_SLOG + RROWS * N_EXP)
#define REPAIR_SMEM ((RSM_ROWS + RROWS) * 4)       // ~108.6 KB

// Compacted list of marginal rows needing exact serial-fp32 recompute.
// Zero-initialized at module load; repair kernel resets counters at exit so
// the zero-at-entry invariant holds across graph replays.
__device__ int g_count;
__device__ int g_done;
__device__ int g_list[T_TOKENS];

static __device__ __forceinline__ uint32_t smem_u32(const void* p) {
    uint32_t a;
    asm("{ .reg .u64 t; cvta.to.shared.u64 t, %1; cvt.u32.u64 %0, t; }"
        : "=r"(a) : "l"(p));
    return a;
}

static __device__ __forceinline__ void ldsm4(uint32_t r[4], uint32_t addr) {
    asm volatile("ldmatrix.sync.aligned.m8n8.x4.shared.b16 {%0,%1,%2,%3}, [%4];"
                 : "=r"(r[0]), "=r"(r[1]), "=r"(r[2]), "=r"(r[3]) : "r"(addr));
}

static __device__ __forceinline__ void mma16816(
    float c[4], const uint32_t a[4], uint32_t b0, uint32_t b1)
{
    asm volatile(
        "mma.sync.aligned.m16n8k16.row.col.f32.f16.f16.f32 "
        "{%0,%1,%2,%3}, {%4,%5,%6,%7}, {%8,%9}, {%0,%1,%2,%3};"
        : "+f"(c[0]), "+f"(c[1]), "+f"(c[2]), "+f"(c[3])
        : "r"(a[0]), "r"(a[1]), "r"(a[2]), "r"(a[3]), "r"(b0), "r"(b1));
}

static __device__ __forceinline__ void cpa16(uint32_t dst, const void* src) {
    asm volatile("cp.async.ca.shared.global [%0], [%1], 16;"
                 :: "r"(dst), "l"(src) : "memory");
}
#define CP_COMMIT() asm volatile("cp.async.commit_group;" ::: "memory")
#define CP_WAIT(n)  asm volatile("cp.async.wait_group %0;" :: "n"(n) : "memory")

// Split 8 fp32 into fp16 hi (16 B) and fp16 lo (16 B).
static __device__ __forceinline__ void cvt8(
    float4 p, float4 q, uint4& hi, uint4& lo)
{
    __half2 h0 = __floats2half2_rn(p.x, p.y);
    __half2 h1 = __floats2half2_rn(p.z, p.w);
    __half2 h2 = __floats2half2_rn(q.x, q.y);
    __half2 h3 = __floats2half2_rn(q.z, q.w);
    float2 f0 = __half22float2(h0), f1 = __half22float2(h1);
    float2 f2 = __half22float2(h2), f3 = __half22float2(h3);
    __half2 l0 = __floats2half2_rn(p.x - f0.x, p.y - f0.y);
    __half2 l1 = __floats2half2_rn(p.z - f1.x, p.w - f1.y);
    __half2 l2 = __floats2half2_rn(q.x - f2.x, q.y - f2.y);
    __half2 l3 = __floats2half2_rn(q.z - f3.x, q.w - f3.y);
    hi.x = *(uint32_t*)&h0; hi.y = *(uint32_t*)&h1;
    hi.z = *(uint32_t*)&h2; hi.w = *(uint32_t*)&h3;
    lo.x = *(uint32_t*)&l0; lo.y = *(uint32_t*)&l1;
    lo.z = *(uint32_t*)&l2; lo.w = *(uint32_t*)&l3;
}

// Shared top-8 + renormalized softmax writer (ties -> lower index).
static __device__ __forceinline__ void topk_and_write(
    const float* v_in, int row, float* vals, float* inds)
{
    float v[N_EXP];
#pragma unroll
    for (int j = 0; j < N_EXP; j++) v[j] = v_in[j];

    float tv[TOPK]; int ti[TOPK];
#pragma unroll
    for (int it = 0; it < TOPK; it++) {
        float bv = -INFINITY; int bi = 0;
#pragma unroll
        for (int j = 0; j < N_EXP; j++)
            if (v[j] > bv) { bv = v[j]; bi = j; }
        tv[it] = bv; ti[it] = bi;
        v[bi] = -INFINITY;
    }

    const float m = tv[0];
    float e[TOPK], s = 0.0f;
#pragma unroll
    for (int i = 0; i < TOPK; i++) { e[i] = expf(tv[i] - m); s += e[i]; }
    const float inv = 1.0f / s;

    *(float4*)(vals + (size_t)row * TOPK) =
        make_float4(e[0]*inv, e[1]*inv, e[2]*inv, e[3]*inv);
    *(float4*)(vals + (size_t)row * TOPK + 4) =
        make_float4(e[4]*inv, e[5]*inv, e[6]*inv, e[7]*inv);
    *(float4*)(inds + (size_t)row * TOPK) =
        make_float4((float)ti[0], (float)ti[1], (float)ti[2], (float)ti[3]);
    *(float4*)(inds + (size_t)row * TOPK + 4) =
        make_float4((float)ti[4], (float)ti[5], (float)ti[6], (float)ti[7]);
}

// ---------------------------------------------------------------------------
// Fused kernel (round-10 config, BM=128): logits = A @ W^T via HMMA fp16
// split (dual accumulators), double-buffered smem, 1 sync per chunk,
// + top-8 + renorm softmax + flagging. HMMA-rate-bound; do not shrink BM.
// ---------------------------------------------------------------------------
__global__ void __launch_bounds__(256, 1)
router_fused_kernel(const float* __restrict__ A,   // [T, H]
                    const float* __restrict__ W,   // [E, H]
                    float* __restrict__ logits,    // [T, E]
                    float* __restrict__ vals,      // [T, 8]
                    float* __restrict__ inds)      // [T, 8]
{
    extern __shared__ char smem[];
    const uint32_t sb = smem_u32(smem);
    const int tid  = threadIdx.x;
    const int wid  = tid >> 5;
    const int lane = tid & 31;
    const int blockRow = blockIdx.x * BM;
    const int mrow = wid * 16;

    float acc[8][4];     // hi*hi   (full magnitude)
    float acc2[8][4];    // hi*lo + lo*hi   (~2^-11 magnitude)
#pragma unroll
    for (int t = 0; t < 8; t++)
#pragma unroll
        for (int j = 0; j < 4; j++) { acc[t][j] = 0.0f; acc2[t][j] = 0.0f; }

    const float* Abase = A + (size_t)blockRow * H_DIM;

    const int ldRowA[4] = { (tid + 0*256) >> 3, (tid + 1*256) >> 3,
                            (tid + 2*256) >> 3, (tid + 3*256) >> 3 };
    const int ldG = tid & 7;

    float4 pa[4][2], pw[2][2];

    // ---- prologue: LDG chunk 0, convert+store into buffer 0
#pragma unroll
    for (int t = 0; t < 4; t++) {
        const float* p = Abase + (size_t)ldRowA[t] * H_DIM + ldG * 8;
        pa[t][0] = *(const float4*)p;
        pa[t][1] = *(const float4*)(p + 4);
    }
#pragma unroll
    for (int t = 0; t < 2; t++) {
        int row = (tid + t * 256) >> 3;
        const float* p = W + (size_t)row * H_DIM + ldG * 8;
        pw[t][0] = *(const float4*)p;
        pw[t][1] = *(const float4*)(p + 4);
    }
#pragma unroll
    for (int t = 0; t < 4; t++) {
        uint4 hi, lo;
        cvt8(pa[t][0], pa[t][1], hi, lo);
        int off = ldRowA[t] * 128 + SWG(ldRowA[t], ldG) * 16;
        *(uint4*)(smem + AHI_OFF(0) + off) = hi;
        *(uint4*)(smem + ALO_OFF(0) + off) = lo;
    }
#pragma unroll
    for (int t = 0; t < 2; t++) {
        int row = (tid + t * 256) >> 3;
        uint4 hi, lo;
        cvt8(pw[t][0], pw[t][1], hi, lo);
        int off = row * 128 + SWG(row, ldG) * 16;
        *(uint4*)(smem + BHI_OFF(0) + off) = hi;
        *(uint4*)(smem + BLO_OFF(0) + off) = lo;
    }

    const int lj  = lane >> 3;
    const int lrr = lane & 7;
    const int jr  = (lj & 1) * 8 + lrr;
    const int jg  = lj >> 1;

    for (int c = 0; c < NCHUNK; c++) {
        const int buf = c & 1;

        // ---- issue next chunk's global loads (consumed after MMA)
        if (c + 1 < NCHUNK) {
            const float* Ab = Abase + (c + 1) * KC;
            const float* Wb = W + (c + 1) * KC;
#pragma unroll
            for (int t = 0; t < 4; t++) {
                const float* p = Ab + (size_t)ldRowA[t] * H_DIM + ldG * 8;
                pa[t][0] = *(const float4*)p;
                pa[t][1] = *(const float4*)(p + 4);
            }
#pragma unroll
            for (int t = 0; t < 2; t++) {
                int row = (tid + t * 256) >> 3;
                const float* p = Wb + (size_t)row * H_DIM + ldG * 8;
                pw[t][0] = *(const float4*)p;
                pw[t][1] = *(const float4*)(p + 4);
            }
        }

        __syncthreads();   // all warps' stores into buf are complete

        // ---- MMA over buf: 4 k16-steps
#pragma unroll
        for (int ks = 0; ks < 4; ks++) {
            const int gk = ks * 2;

            uint32_t ah[4], al[4];
            {
                int arow = mrow + jr;
                int ag   = gk + jg;
                uint32_t off = arow * 128 + SWG(arow, ag) * 16;
                ldsm4(ah, sb + AHI_OFF(buf) + off);
                ldsm4(al, sb + ALO_OFF(buf) + off);
            }

            uint32_t bh[8][2], bl[8][2];
#pragma unroll
            for (int p = 0; p < 4; p++) {
                int brow = p * 16 + jr;
                int bg   = gk + jg;
                uint32_t off = brow * 128 + SWG(brow, bg) * 16;
                uint32_t r[4];
                ldsm4(r, sb + BHI_OFF(buf) + off);
                bh[2*p][0] = r[0]; bh[2*p][1] = r[2];
                bh[2*p+1][0] = r[1]; bh[2*p+1][1] = r[3];
                ldsm4(r, sb + BLO_OFF(buf) + off);
                bl[2*p][0] = r[0]; bl[2*p][1] = r[2];
                bl[2*p+1][0] = r[1]; bl[2*p+1][1] = r[3];
            }

#pragma unroll
            for (int t = 0; t < 8; t++) {
                mma16816(acc[t],  ah, bh[t][0], bh[t][1]);   // hi*hi -> acc
                mma16816(acc2[t], ah, bl[t][0], bl[t][1]);   // hi*lo -> acc2
                mma16816(acc2[t], al, bh[t][0], bh[t][1]);   // lo*hi -> acc2
            }
        }

        // ---- convert + store next chunk into the other buffer
        if (c + 1 < NCHUNK) {
            const int nbuf = buf ^ 1;
#pragma unroll
            for (int t = 0; t < 4; t++) {
                uint4 hi, lo;
                cvt8(pa[t][0], pa[t][1], hi, lo);
                int off = ldRowA[t] * 128 + SWG(ldRowA[t], ldG) * 16;
                *(uint4*)(smem + AHI_OFF(nbuf) + off) = hi;
                *(uint4*)(smem + ALO_OFF(nbuf) + off) = lo;
            }
#pragma unroll
            for (int t = 0; t < 2; t++) {
                int row = (tid + t * 256) >> 3;
                uint4 hi, lo;
                cvt8(pw[t][0], pw[t][1], hi, lo);
                int off = row * 128 + SWG(row, ldG) * 16;
                *(uint4*)(smem + BHI_OFF(nbuf) + off) = hi;
                *(uint4*)(smem + BLO_OFF(nbuf) + off) = lo;
            }
        }
    }

    // Fold the small-term accumulator in once.
#pragma unroll
    for (int t = 0; t < 8; t++)
#pragma unroll
        for (int j = 0; j < 4; j++) acc[t][j] += acc2[t][j];

    __syncthreads();   // all warps done with the final MMA buffer

    // ---------------- Epilogue ----------------
    float* lsm = (float*)smem;   // [128][68] f32 (34816 B)
    {
        const int group = lane >> 2, tig = lane & 3;
#pragma unroll
        for (int t = 0; t < 8; t++) {
            int col = t * 8 + 2 * tig;
            *(float2*)&lsm[(mrow + group)     * 68 + col] =
                make_float2(acc[t][0], acc[t][1]);
            *(float2*)&lsm[(mrow + group + 8) * 68 + col] =
                make_float2(acc[t][2], acc[t][3]);
        }
    }
    __syncthreads();

    // Coalesced logits store
#pragma unroll
    for (int t = 0; t < 8; t++) {
        int i = tid + t * 256;
        int row = i >> 4, q = i & 15;
        float4 v = *(float4*)&lsm[row * 68 + q * 4];
        *(float4*)&logits[(size_t)(blockRow + row) * N_EXP + q * 4] = v;
    }

    // Top-8 + renorm softmax + marginal-row flag: threads 0..127, one row each
    if (tid < BM) {
        const int row = blockRow + tid;
        float v[N_EXP];
#pragma unroll
        for (int j = 0; j < N_EXP; j++) v[j] = lsm[tid * 68 + j];

        float tv[TOPK + 1]; int ti[TOPK];
#pragma unroll
        for (int it = 0; it < TOPK; it++) {
            float bv = -INFINITY; int bi = 0;
#pragma unroll
            for (int j = 0; j < N_EXP; j++)
                if (v[j] > bv) { bv = v[j]; bi = j; }
            tv[it] = bv; ti[it] = bi;
            v[bi] = -INFINITY;
        }
        {
            float bv = -INFINITY;
#pragma unroll
            for (int j = 0; j < N_EXP; j++) bv = fmaxf(bv, v[j]);
            tv[TOPK] = bv;
        }

        float min_gap = INFINITY;
#pragma unroll
        for (int i = 0; i < TOPK; i++) min_gap = fminf(min_gap, tv[i] - tv[i + 1]);
        if (min_gap < GAP_THR) {
            int idx = atomicAdd(&g_count, 1);
            g_list[idx] = row;
        }

        const float m = tv[0];
        float e[TOPK], s = 0.0f;
#pragma unroll
        for (int i = 0; i < TOPK; i++) { e[i] = expf(tv[i] - m); s += e[i]; }
        const float inv = 1.0f / s;

        *(float4*)(vals + (size_t)row * TOPK) =
            make_float4(e[0]*inv, e[1]*inv, e[2]*inv, e[3]*inv);
        *(float4*)(vals + (size_t)row * TOPK + 4) =
            make_float4(e[4]*inv, e[5]*inv, e[6]*inv, e[7]*inv);
        *(float4*)(inds + (size_t)row * TOPK) =
            make_float4((float)ti[0], (float)ti[1], (float)ti[2], (float)ti[3]);
        *(float4*)(inds + (size_t)row * TOPK + 4) =
            make_float4((float)ti[4], (float)ti[5], (float)ti[6], (float)ti[7]);
    }
}

// ---------------------------------------------------------------------------
// Repair kernel v4: serial-in-k fp32 recompute of marginal rows.
// 256 threads = (expert e = tid&63, row r = tid>>6); ONE chain per thread.
// 4 rows per group, 3-deep cp.async pipeline, grid 64.
// k-order 0..2047 strictly serial per chain -> bitwise-stable results.
// ---------------------------------------------------------------------------
__global__ void __launch_bounds__(RTHREADS)
router_repair_kernel(const float* __restrict__ A,
                     const float* __restrict__ W,
                     float* __restrict__ logits,
                     float* __restrict__ vals,
                     float* __restrict__ inds)
{
    extern __shared__ float rs[];
    float* slog   = rs + RSM_SLOG;        // [4][64]
    int*   rows_s = (int*)(rs + RSM_ROWS);

    const uint32_t sbase = smem_u32(rs);
    const int tid = threadIdx.x;
    const int e   = tid & 63;             // expert
    const int r   = tid >> 6;             // row within group (0..3)

    const int count = g_count;
    const int ngroups = (count + RROWS - 1) / RROWS;

    // prefetch chunk c into buffer b
    // W: 64 rows x 32 float4 = 2048 / 256 thr = 8 each; A: 128 float4, thr<128
#define RP_PREFETCH(c, b) do {                                               \
        const float* Wc = W + (c) * 128;                                     \
        uint32_t swb = sbase + (b) * (RSM_SWBUF * 4);                        \
        _Pragma("unroll")                                                    \
        for (int j = 0; j < 8; j++) {                                        \
            int i = tid + RTHREADS * j;                                      \
            int row = i >> 5, q = i & 31;                                    \
            cpa16(swb + (row * SW_STR + q * 4) * 4,                          \
                  Wc + (size_t)row * H_DIM + q * 4);                         \
        }                                                                    \
        if (tid < RROWS * 32) {                                              \
            int rr = tid >> 5, q = tid & 31;                                 \
            int row = rows_s[rr]; if (row < 0) row = 0;                      \
            uint32_t sab = sbase + (RSM_SA + (b) * (RROWS * 128)             \
                                    + rr * 128 + q * 4) * 4;                 \
            cpa16(sab, A + (size_t)row * H_DIM + (c) * 128 + q * 4);         \
        }                                                                    \
        CP_COMMIT();                                                         \
    } while (0)

    for (int g = blockIdx.x; g < ngroups; g += gridDim.x) {
        __syncthreads();                  // protect rows_s/slog reuse
        if (tid < RROWS) {
            int i = g * RROWS + tid;
            rows_s[tid] = (i < count) ? g_list[i] : -1;
        }
        __syncthreads();

        RP_PREFETCH(0, 0);
        RP_PREFETCH(1, 1);

        float acc = 0.0f;

        for (int c = 0; c < 16; c++) {
            const int buf = c % 3;
            if (c < 15) { CP_WAIT(1); }   // chunk c complete (c+1 may fly)
            else        { CP_WAIT(0); }
            __syncthreads();              // chunk c visible; buf (c+2)%3 free
            if (c + 2 < 16) RP_PREFETCH(c + 2, (c + 2) % 3);

            const float* swr = rs + buf * RSM_SWBUF + e * SW_STR;
            const float* sa  = rs + RSM_SA + buf * (RROWS * 128) + r * 128;

#pragma unroll
            for (int k4 = 0; k4 < 32; k4++) {
                float4 w4 = *(const float4*)(swr + k4 * 4);
                float4 a4 = *(const float4*)(sa + k4 * 4);
                acc = fmaf(a4.x, w4.x, acc);
                acc = fmaf(a4.y, w4.y, acc);
                acc = fmaf(a4.z, w4.z, acc);
                acc = fmaf(a4.w, w4.w, acc);
            }
        }

        slog[r * N_EXP + e] = acc;
        {
            int row = rows_s[r];
            if (row >= 0) logits[(size_t)row * N_EXP + e] = acc;
        }
        __syncthreads();

        if (tid < RROWS && rows_s[tid] >= 0)
            topk_and_write(slog + tid * N_EXP, rows_s[tid], vals, inds);
    }
#undef RP_PREFETCH

    // Reset counters for the next replay. Every block read g_count before
    // incrementing g_done, so the last-arriving block can safely zero both.
    if (tid == 0) {
        int old = atomicAdd(&g_done, 1);
        if (old == (int)gridDim.x - 1) {
            g_count = 0;
            g_done  = 0;
        }
    }
}

// ---------------------------------------------------------------------------
// Launch
// ---------------------------------------------------------------------------
extern "C" void kernel_launch(void* const* d_in, const int* in_sizes, int n_in,
                              void* d_out, int out_size)
{
    const float* hidden = (const float*)d_in[0];   // [16384, 2048]
    const float* weight = (const float*)d_in[1];   // [64, 2048]
    float* out = (float*)d_out;

    float* logits = out;                                 // 16384*64
    float* vals   = out + (size_t)T_TOKENS * N_EXP;      // 16384*8
    float* inds   = vals + (size_t)T_TOKENS * TOPK;      // 16384*8

    cudaFuncSetAttribute(router_fused_kernel,
                         cudaFuncAttributeMaxDynamicSharedMemorySize, SMEM_TOTAL);
    router_fused_kernel<<<T_TOKENS / BM, 256, SMEM_TOTAL>>>(
        hidden, weight, logits, vals, inds);

    cudaFuncSetAttribute(router_repair_kernel,
                         cudaFuncAttributeMaxDynamicSharedMemorySize, REPAIR_SMEM);
    router_repair_kernel<<<RGRID, RTHREADS, REPAIR_SMEM>>>(
        hidden, weight, logits, vals, inds);
}

// round 15
// speedup vs baseline: 1.0550x; 1.0126x over previous
#include <cuda_runtime.h>
#include <cuda_fp16.h>
#include <cstdint>
#include <math.h>

// ---------------------------------------------------------------------------
// Problem constants
// ---------------------------------------------------------------------------
#define T_TOKENS 16384
#define H_DIM    2048
#define N_EXP    64
#define TOPK     8
#define KC       64                  // fp32 k-elements per chunk
#define NCHUNK   (H_DIM / KC)        // 32
#define BM       128                 // tokens per CTA
#define GAP_THR  3.0e-5f             // marginal-row flag threshold (abs logit)

// SMEM: double-buffered fp16 tiles, 128 B per row (64 halves), swizzled.
//   per buffer: A_hi 16K | A_lo 16K | B_hi 8K | B_lo 8K = 48 KB
#define BUFSZ    49152
#define AHI_OFF(b)  ((b) * BUFSZ + 0)
#define ALO_OFF(b)  ((b) * BUFSZ + 16384)
#define BHI_OFF(b)  ((b) * BUFSZ + 32768)
#define BLO_OFF(b)  ((b) * BUFSZ + 40960)
#define SMEM_TOTAL  (2 * BUFSZ)      // 98304; epilogue reuses [0,34816) as f32

// 16-byte-granule XOR swizzle within a 128-byte row
#define SWG(row, g) ((g) ^ ((row) & 7))

// ---------------------------------------------------------------------------
// Repair kernel sizing (v5: 4 rows/group, 256 threads, 1 chain/thread,
// 5-buffer / 4-ahead cp.async pipeline to cover DRAM latency)
// ---------------------------------------------------------------------------
#define RGRID     64
#define RTHREADS  256
#define RROWS     4
#define RDEPTH    5                                // W/A buffers
#define RAHEAD    4                                // chunks in flight
#define SW_STR    132                              // padded floats per W row
#define RSM_SWBUF (64 * SW_STR)                    // 8448 floats per W buffer
#define RSM_SA    (RDEPTH * RSM_SWBUF)             // A bufs after W bufs
#define RSM_SLOG  (RSM_SA + RDEPTH * RROWS * 128)  // slog after A bufs
#define RSM_ROWS  (RSM_SLOG + RROWS * N_EXP)
#define REPAIR_SMEM ((RSM_ROWS + RROWS) * 4)       // ~180.5 KB

// Compacted list of marginal rows needing exact serial-fp32 recompute.
// Zero-initialized at module load; repair kernel resets counters at exit so
// the zero-at-entry invariant holds across graph replays.
__device__ int g_count;
__device__ int g_done;
__device__ int g_list[T_TOKENS];

static __device__ __forceinline__ uint32_t smem_u32(const void* p) {
    uint32_t a;
    asm("{ .reg .u64 t; cvta.to.shared.u64 t, %1; cvt.u32.u64 %0, t; }"
        : "=r"(a) : "l"(p));
    return a;
}

static __device__ __forceinline__ void ldsm4(uint32_t r[4], uint32_t addr) {
    asm volatile("ldmatrix.sync.aligned.m8n8.x4.shared.b16 {%0,%1,%2,%3}, [%4];"
                 : "=r"(r[0]), "=r"(r[1]), "=r"(r[2]), "=r"(r[3]) : "r"(addr));
}

static __device__ __forceinline__ void mma16816(
    float c[4], const uint32_t a[4], uint32_t b0, uint32_t b1)
{
    asm volatile(
        "mma.sync.aligned.m16n8k16.row.col.f32.f16.f16.f32 "
        "{%0,%1,%2,%3}, {%4,%5,%6,%7}, {%8,%9}, {%0,%1,%2,%3};"
        : "+f"(c[0]), "+f"(c[1]), "+f"(c[2]), "+f"(c[3])
        : "r"(a[0]), "r"(a[1]), "r"(a[2]), "r"(a[3]), "r"(b0), "r"(b1));
}

static __device__ __forceinline__ void cpa16(uint32_t dst, const void* src) {
    asm volatile("cp.async.ca.shared.global [%0], [%1], 16;"
                 :: "r"(dst), "l"(src) : "memory");
}
#define CP_COMMIT() asm volatile("cp.async.commit_group;" ::: "memory")
#define CP_WAIT(n)  asm volatile("cp.async.wait_group %0;" :: "n"(n) : "memory")

// Split 8 fp32 into fp16 hi (16 B) and fp16 lo (16 B).
static __device__ __forceinline__ void cvt8(
    float4 p, float4 q, uint4& hi, uint4& lo)
{
    __half2 h0 = __floats2half2_rn(p.x, p.y);
    __half2 h1 = __floats2half2_rn(p.z, p.w);
    __half2 h2 = __floats2half2_rn(q.x, q.y);
    __half2 h3 = __floats2half2_rn(q.z, q.w);
    float2 f0 = __half22float2(h0), f1 = __half22float2(h1);
    float2 f2 = __half22float2(h2), f3 = __half22float2(h3);
    __half2 l0 = __floats2half2_rn(p.x - f0.x, p.y - f0.y);
    __half2 l1 = __floats2half2_rn(p.z - f1.x, p.w - f1.y);
    __half2 l2 = __floats2half2_rn(q.x - f2.x, q.y - f2.y);
    __half2 l3 = __floats2half2_rn(q.z - f3.x, q.w - f3.y);
    hi.x = *(uint32_t*)&h0; hi.y = *(uint32_t*)&h1;
    hi.z = *(uint32_t*)&h2; hi.w = *(uint32_t*)&h3;
    lo.x = *(uint32_t*)&l0; lo.y = *(uint32_t*)&l1;
    lo.z = *(uint32_t*)&l2; lo.w = *(uint32_t*)&l3;
}

// Shared top-8 + renormalized softmax writer (ties -> lower index).
static __device__ __forceinline__ void topk_and_write(
    const float* v_in, int row, float* vals, float* inds)
{
    float v[N_EXP];
#pragma unroll
    for (int j = 0; j < N_EXP; j++) v[j] = v_in[j];

    float tv[TOPK]; int ti[TOPK];
#pragma unroll
    for (int it = 0; it < TOPK; it++) {
        float bv = -INFINITY; int bi = 0;
#pragma unroll
        for (int j = 0; j < N_EXP; j++)
            if (v[j] > bv) { bv = v[j]; bi = j; }
        tv[it] = bv; ti[it] = bi;
        v[bi] = -INFINITY;
    }

    const float m = tv[0];
    float e[TOPK], s = 0.0f;
#pragma unroll
    for (int i = 0; i < TOPK; i++) { e[i] = expf(tv[i] - m); s += e[i]; }
    const float inv = 1.0f / s;

    *(float4*)(vals + (size_t)row * TOPK) =
        make_float4(e[0]*inv, e[1]*inv, e[2]*inv, e[3]*inv);
    *(float4*)(vals + (size_t)row * TOPK + 4) =
        make_float4(e[4]*inv, e[5]*inv, e[6]*inv, e[7]*inv);
    *(float4*)(inds + (size_t)row * TOPK) =
        make_float4((float)ti[0], (float)ti[1], (float)ti[2], (float)ti[3]);
    *(float4*)(inds + (size_t)row * TOPK + 4) =
        make_float4((float)ti[4], (float)ti[5], (float)ti[6], (float)ti[7]);
}

// ---------------------------------------------------------------------------
// Fused kernel (round-10 config, BM=128): logits = A @ W^T via HMMA fp16
// split (dual accumulators), double-buffered smem, 1 sync per chunk,
// + top-8 + renorm softmax + flagging. HMMA-rate-bound; do not shrink BM.
// ---------------------------------------------------------------------------
__global__ void __launch_bounds__(256, 1)
router_fused_kernel(const float* __restrict__ A,   // [T, H]
                    const float* __restrict__ W,   // [E, H]
                    float* __restrict__ logits,    // [T, E]
                    float* __restrict__ vals,      // [T, 8]
                    float* __restrict__ inds)      // [T, 8]
{
    extern __shared__ char smem[];
    const uint32_t sb = smem_u32(smem);
    const int tid  = threadIdx.x;
    const int wid  = tid >> 5;
    const int lane = tid & 31;
    const int blockRow = blockIdx.x * BM;
    const int mrow = wid * 16;

    float acc[8][4];     // hi*hi   (full magnitude)
    float acc2[8][4];    // hi*lo + lo*hi   (~2^-11 magnitude)
#pragma unroll
    for (int t = 0; t < 8; t++)
#pragma unroll
        for (int j = 0; j < 4; j++) { acc[t][j] = 0.0f; acc2[t][j] = 0.0f; }

    const float* Abase = A + (size_t)blockRow * H_DIM;

    const int ldRowA[4] = { (tid + 0*256) >> 3, (tid + 1*256) >> 3,
                            (tid + 2*256) >> 3, (tid + 3*256) >> 3 };
    const int ldG = tid & 7;

    float4 pa[4][2], pw[2][2];

    // ---- prologue: LDG chunk 0, convert+store into buffer 0
#pragma unroll
    for (int t = 0; t < 4; t++) {
        const float* p = Abase + (size_t)ldRowA[t] * H_DIM + ldG * 8;
        pa[t][0] = *(const float4*)p;
        pa[t][1] = *(const float4*)(p + 4);
    }
#pragma unroll
    for (int t = 0; t < 2; t++) {
        int row = (tid + t * 256) >> 3;
        const float* p = W + (size_t)row * H_DIM + ldG * 8;
        pw[t][0] = *(const float4*)p;
        pw[t][1] = *(const float4*)(p + 4);
    }
#pragma unroll
    for (int t = 0; t < 4; t++) {
        uint4 hi, lo;
        cvt8(pa[t][0], pa[t][1], hi, lo);
        int off = ldRowA[t] * 128 + SWG(ldRowA[t], ldG) * 16;
        *(uint4*)(smem + AHI_OFF(0) + off) = hi;
        *(uint4*)(smem + ALO_OFF(0) + off) = lo;
    }
#pragma unroll
    for (int t = 0; t < 2; t++) {
        int row = (tid + t * 256) >> 3;
        uint4 hi, lo;
        cvt8(pw[t][0], pw[t][1], hi, lo);
        int off = row * 128 + SWG(row, ldG) * 16;
        *(uint4*)(smem + BHI_OFF(0) + off) = hi;
        *(uint4*)(smem + BLO_OFF(0) + off) = lo;
    }

    const int lj  = lane >> 3;
    const int lrr = lane & 7;
    const int jr  = (lj & 1) * 8 + lrr;
    const int jg  = lj >> 1;

    for (int c = 0; c < NCHUNK; c++) {
        const int buf = c & 1;

        // ---- issue next chunk's global loads (consumed after MMA)
        if (c + 1 < NCHUNK) {
            const float* Ab = Abase + (c + 1) * KC;
            const float* Wb = W + (c + 1) * KC;
#pragma unroll
            for (int t = 0; t < 4; t++) {
                const float* p = Ab + (size_t)ldRowA[t] * H_DIM + ldG * 8;
                pa[t][0] = *(const float4*)p;
                pa[t][1] = *(const float4*)(p + 4);
            }
#pragma unroll
            for (int t = 0; t < 2; t++) {
                int row = (tid + t * 256) >> 3;
                const float* p = Wb + (size_t)row * H_DIM + ldG * 8;
                pw[t][0] = *(const float4*)p;
                pw[t][1] = *(const float4*)(p + 4);
            }
        }

        __syncthreads();   // all warps' stores into buf are complete

        // ---- MMA over buf: 4 k16-steps
#pragma unroll
        for (int ks = 0; ks < 4; ks++) {
            const int gk = ks * 2;

            uint32_t ah[4], al[4];
            {
                int arow = mrow + jr;
                int ag   = gk + jg;
                uint32_t off = arow * 128 + SWG(arow, ag) * 16;
                ldsm4(ah, sb + AHI_OFF(buf) + off);
                ldsm4(al, sb + ALO_OFF(buf) + off);
            }

            uint32_t bh[8][2], bl[8][2];
#pragma unroll
            for (int p = 0; p < 4; p++) {
                int brow = p * 16 + jr;
                int bg   = gk + jg;
                uint32_t off = brow * 128 + SWG(brow, bg) * 16;
                uint32_t r[4];
                ldsm4(r, sb + BHI_OFF(buf) + off);
                bh[2*p][0] = r[0]; bh[2*p][1] = r[2];
                bh[2*p+1][0] = r[1]; bh[2*p+1][1] = r[3];
                ldsm4(r, sb + BLO_OFF(buf) + off);
                bl[2*p][0] = r[0]; bl[2*p][1] = r[2];
                bl[2*p+1][0] = r[1]; bl[2*p+1][1] = r[3];
            }

#pragma unroll
            for (int t = 0; t < 8; t++) {
                mma16816(acc[t],  ah, bh[t][0], bh[t][1]);   // hi*hi -> acc
                mma16816(acc2[t], ah, bl[t][0], bl[t][1]);   // hi*lo -> acc2
                mma16816(acc2[t], al, bh[t][0], bh[t][1]);   // lo*hi -> acc2
            }
        }

        // ---- convert + store next chunk into the other buffer
        if (c + 1 < NCHUNK) {
            const int nbuf = buf ^ 1;
#pragma unroll
            for (int t = 0; t < 4; t++) {
                uint4 hi, lo;
                cvt8(pa[t][0], pa[t][1], hi, lo);
                int off = ldRowA[t] * 128 + SWG(ldRowA[t], ldG) * 16;
                *(uint4*)(smem + AHI_OFF(nbuf) + off) = hi;
                *(uint4*)(smem + ALO_OFF(nbuf) + off) = lo;
            }
#pragma unroll
            for (int t = 0; t < 2; t++) {
                int row = (tid + t * 256) >> 3;
                uint4 hi, lo;
                cvt8(pw[t][0], pw[t][1], hi, lo);
                int off = row * 128 + SWG(row, ldG) * 16;
                *(uint4*)(smem + BHI_OFF(nbuf) + off) = hi;
                *(uint4*)(smem + BLO_OFF(nbuf) + off) = lo;
            }
        }
    }

    // Fold the small-term accumulator in once.
#pragma unroll
    for (int t = 0; t < 8; t++)
#pragma unroll
        for (int j = 0; j < 4; j++) acc[t][j] += acc2[t][j];

    __syncthreads();   // all warps done with the final MMA buffer

    // ---------------- Epilogue ----------------
    float* lsm = (float*)smem;   // [128][68] f32 (34816 B)
    {
        const int group = lane >> 2, tig = lane & 3;
#pragma unroll
        for (int t = 0; t < 8; t++) {
            int col = t * 8 + 2 * tig;
            *(float2*)&lsm[(mrow + group)     * 68 + col] =
                make_float2(acc[t][0], acc[t][1]);
            *(float2*)&lsm[(mrow + group + 8) * 68 + col] =
                make_float2(acc[t][2], acc[t][3]);
        }
    }
    __syncthreads();

    // Coalesced logits store
#pragma unroll
    for (int t = 0; t < 8; t++) {
        int i = tid + t * 256;
        int row = i >> 4, q = i & 15;
        float4 v = *(float4*)&lsm[row * 68 + q * 4];
        *(float4*)&logits[(size_t)(blockRow + row) * N_EXP + q * 4] = v;
    }

    // Top-8 + renorm softmax + marginal-row flag: threads 0..127, one row each
    if (tid < BM) {
        const int row = blockRow + tid;
        float v[N_EXP];
#pragma unroll
        for (int j = 0; j < N_EXP; j++) v[j] = lsm[tid * 68 + j];

        float tv[TOPK + 1]; int ti[TOPK];
#pragma unroll
        for (int it = 0; it < TOPK; it++) {
            float bv = -INFINITY; int bi = 0;
#pragma unroll
            for (int j = 0; j < N_EXP; j++)
                if (v[j] > bv) { bv = v[j]; bi = j; }
            tv[it] = bv; ti[it] = bi;
            v[bi] = -INFINITY;
        }
        {
            float bv = -INFINITY;
#pragma unroll
            for (int j = 0; j < N_EXP; j++) bv = fmaxf(bv, v[j]);
            tv[TOPK] = bv;
        }

        float min_gap = INFINITY;
#pragma unroll
        for (int i = 0; i < TOPK; i++) min_gap = fminf(min_gap, tv[i] - tv[i + 1]);
        if (min_gap < GAP_THR) {
            int idx = atomicAdd(&g_count, 1);
            g_list[idx] = row;
        }

        const float m = tv[0];
        float e[TOPK], s = 0.0f;
#pragma unroll
        for (int i = 0; i < TOPK; i++) { e[i] = expf(tv[i] - m); s += e[i]; }
        const float inv = 1.0f / s;

        *(float4*)(vals + (size_t)row * TOPK) =
            make_float4(e[0]*inv, e[1]*inv, e[2]*inv, e[3]*inv);
        *(float4*)(vals + (size_t)row * TOPK + 4) =
            make_float4(e[4]*inv, e[5]*inv, e[6]*inv, e[7]*inv);
        *(float4*)(inds + (size_t)row * TOPK) =
            make_float4((float)ti[0], (float)ti[1], (float)ti[2], (float)ti[3]);
        *(float4*)(inds + (size_t)row * TOPK + 4) =
            make_float4((float)ti[4], (float)ti[5], (float)ti[6], (float)ti[7]);
    }
}

// ---------------------------------------------------------------------------
// Repair kernel v5: serial-in-k fp32 recompute of marginal rows.
// 256 threads = (expert e = tid&63, row r = tid>>6); ONE chain per thread.
// 4 rows/group; 5-buffer cp.async pipeline with 4 chunks in flight to cover
// DRAM latency (W is L2-cold after the fused kernel's 128MB A stream).
// k-order 0..2047 strictly serial per chain -> bitwise-stable results.
// ---------------------------------------------------------------------------
__global__ void __launch_bounds__(RTHREADS)
router_repair_kernel(const float* __restrict__ A,
                     const float* __restrict__ W,
                     float* __restrict__ logits,
                     float* __restrict__ vals,
                     float* __restrict__ inds)
{
    extern __shared__ float rs[];
    float* slog   = rs + RSM_SLOG;        // [4][64]
    int*   rows_s = (int*)(rs + RSM_ROWS);

    const uint32_t sbase = smem_u32(rs);
    const int tid = threadIdx.x;
    const int e   = tid & 63;             // expert
    const int r   = tid >> 6;             // row within group (0..3)

    const int count = g_count;
    const int ngroups = (count + RROWS - 1) / RROWS;

    // prefetch chunk c into buffer b
    // W: 64 rows x 32 float4 = 2048 / 256 thr = 8 each; A: 128 float4, thr<128
#define RP_PREFETCH(c, b) do {                                               \
        const float* Wc = W + (c) * 128;                                     \
        uint32_t swb = sbase + (b) * (RSM_SWBUF * 4);                        \
        _Pragma("unroll")                                                    \
        for (int j = 0; j < 8; j++) {                                        \
            int i = tid + RTHREADS * j;                                      \
            int row = i >> 5, q = i & 31;                                    \
            cpa16(swb + (row * SW_STR + q * 4) * 4,                          \
                  Wc + (size_t)row * H_DIM + q * 4);                         \
        }                                                                    \
        if (tid < RROWS * 32) {                                              \
            int rr = tid >> 5, q = tid & 31;                                 \
            int row = rows_s[rr]; if (row < 0) row = 0;                      \
            uint32_t sab = sbase + (RSM_SA + (b) * (RROWS * 128)             \
                                    + rr * 128 + q * 4) * 4;                 \
            cpa16(sab, A + (size_t)row * H_DIM + (c) * 128 + q * 4);         \
        }                                                                    \
        CP_COMMIT();                                                         \
    } while (0)

    for (int g = blockIdx.x; g < ngroups; g += gridDim.x) {
        __syncthreads();                  // protect rows_s/slog reuse
        if (tid < RROWS) {
            int i = g * RROWS + tid;
            rows_s[tid] = (i < count) ? g_list[i] : -1;
        }
        __syncthreads();

        // fill the pipeline: 4 chunks in flight
        RP_PREFETCH(0, 0);
        RP_PREFETCH(1, 1);
        RP_PREFETCH(2, 2);
        RP_PREFETCH(3, 3);

        float acc = 0.0f;

        for (int c = 0; c < 16; c++) {
            const int buf = c % RDEPTH;
            if (c < 12) { CP_WAIT(3); }   // chunk c complete (c+1..c+3 fly)
            else if (c == 12) { CP_WAIT(3); }
            else if (c == 13) { CP_WAIT(2); }
            else if (c == 14) { CP_WAIT(1); }
            else              { CP_WAIT(0); }
            __syncthreads();              // chunk c visible; buf (c+4)%5 free
            if (c + RAHEAD < 16) RP_PREFETCH(c + RAHEAD, (c + RAHEAD) % RDEPTH);

            const float* swr = rs + buf * RSM_SWBUF + e * SW_STR;
            const float* sa  = rs + RSM_SA + buf * (RROWS * 128) + r * 128;

#pragma unroll
            for (int k4 = 0; k4 < 32; k4++) {
                float4 w4 = *(const float4*)(swr + k4 * 4);
                float4 a4 = *(const float4*)(sa + k4 * 4);
                acc = fmaf(a4.x, w4.x, acc);
                acc = fmaf(a4.y, w4.y, acc);
                acc = fmaf(a4.z, w4.z, acc);
                acc = fmaf(a4.w, w4.w, acc);
            }
        }

        slog[r * N_EXP + e] = acc;
        {
            int row = rows_s[r];
            if (row >= 0) logits[(size_t)row * N_EXP + e] = acc;
        }
        __syncthreads();

        if (tid < RROWS && rows_s[tid] >= 0)
            topk_and_write(slog + tid * N_EXP, rows_s[tid], vals, inds);
    }
#undef RP_PREFETCH

    // Reset counters for the next replay. Every block read g_count before
    // incrementing g_done, so the last-arriving block can safely zero both.
    if (tid == 0) {
        int old = atomicAdd(&g_done, 1);
        if (old == (int)gridDim.x - 1) {
            g_count = 0;
            g_done  = 0;
        }
    }
}

// ---------------------------------------------------------------------------
// Launch
// ---------------------------------------------------------------------------
extern "C" void kernel_launch(void* const* d_in, const int* in_sizes, int n_in,
                              void* d_out, int out_size)
{
    const float* hidden = (const float*)d_in[0];   // [16384, 2048]
    const float* weight = (const float*)d_in[1];   // [64, 2048]
    float* out = (float*)d_out;

    float* logits = out;                                 // 16384*64
    float* vals   = out + (size_t)T_TOKENS * N_EXP;      // 16384*8
    float* inds   = vals + (size_t)T_TOKENS * TOPK;      // 16384*8

    cudaFuncSetAttribute(router_fused_kernel,
                         cudaFuncAttributeMaxDynamicSharedMemorySize, SMEM_TOTAL);
    router_fused_kernel<<<T_TOKENS / BM, 256, SMEM_TOTAL>>>(
        hidden, weight, logits, vals, inds);

    cudaFuncSetAttribute(router_repair_kernel,
                         cudaFuncAttributeMaxDynamicSharedMemorySize, REPAIR_SMEM);
    router_repair_kernel<<<RGRID, RTHREADS, REPAIR_SMEM>>>(
        hidden, weight, logits, vals, inds);
}

// round 17
// speedup vs baseline: 1.0721x; 1.0162x over previous
#include <cuda_runtime.h>
#include <cuda_fp16.h>
#include <cstdint>
#include <math.h>

// ---------------------------------------------------------------------------
// Problem constants
// ---------------------------------------------------------------------------
#define T_TOKENS 16384
#define H_DIM    2048
#define N_EXP    64
#define TOPK     8
#define KC       64                  // fp32 k-elements per GEMM chunk
#define NCHUNK   (H_DIM / KC)        // 32
#define BM       128                 // tokens per CTA
#define GAP_THR  3.0e-5f             // marginal-row flag threshold (abs logit)

// SMEM: double-buffered fp16 tiles, 128 B per row (64 halves), swizzled.
//   per buffer: A_hi 16K | A_lo 16K | B_hi 8K | B_lo 8K = 48 KB
#define BUFSZ    49152
#define AHI_OFF(b)  ((b) * BUFSZ + 0)
#define ALO_OFF(b)  ((b) * BUFSZ + 16384)
#define BHI_OFF(b)  ((b) * BUFSZ + 32768)
#define BLO_OFF(b)  ((b) * BUFSZ + 40960)
#define SMEM_TOTAL  (2 * BUFSZ)      // 98304 bytes

// 16-byte-granule XOR swizzle within a 128-byte row
#define SWG(row, g) ((g) ^ ((row) & 7))

// ---------------------------------------------------------------------------
// In-CTA repair layout (float offsets within the SAME dynamic smem, reused
// after the epilogue). 32 k-chunks of 64 floats; 3-buffer cp.async pipeline.
//   W buf: 64 experts x 68 floats (stride-68 pad) = 4352 floats
//   A buf: 4 rows x 64 floats = 256 floats
// ---------------------------------------------------------------------------
#define RP_KC     64
#define RP_NCH    32
#define RP_WSTR   68
#define RP_WBUF   (N_EXP * RP_WSTR)                  // 4352
#define RP_W      0                                  // 3 bufs -> 13056
#define RP_A      (3 * RP_WBUF)                      // 13056; 3 bufs -> 13824
#define RP_SLOG   (RP_A + 3 * 4 * RP_KC)             // 13824 .. 14080
#define RP_LIST   (RP_SLOG + 4 * N_EXP)              // 14080 .. 14208 (ints)
#define RP_CNT    (RP_LIST + BM)                     // 14208 (int)
// highest float index 14209 -> 56836 bytes < 98304  OK
// (lsm = [128][68] f32 occupies float idx < 8704; RP_SLOG.. are disjoint)

static __device__ __forceinline__ uint32_t smem_u32(const void* p) {
    uint32_t a;
    asm("{ .reg .u64 t; cvta.to.shared.u64 t, %1; cvt.u32.u64 %0, t; }"
        : "=r"(a) : "l"(p));
    return a;
}

static __device__ __forceinline__ void ldsm4(uint32_t r[4], uint32_t addr) {
    asm volatile("ldmatrix.sync.aligned.m8n8.x4.shared.b16 {%0,%1,%2,%3}, [%4];"
                 : "=r"(r[0]), "=r"(r[1]), "=r"(r[2]), "=r"(r[3]) : "r"(addr));
}

static __device__ __forceinline__ void mma16816(
    float c[4], const uint32_t a[4], uint32_t b0, uint32_t b1)
{
    asm volatile(
        "mma.sync.aligned.m16n8k16.row.col.f32.f16.f16.f32 "
        "{%0,%1,%2,%3}, {%4,%5,%6,%7}, {%8,%9}, {%0,%1,%2,%3};"
        : "+f"(c[0]), "+f"(c[1]), "+f"(c[2]), "+f"(c[3])
        : "r"(a[0]), "r"(a[1]), "r"(a[2]), "r"(a[3]), "r"(b0), "r"(b1));
}

static __device__ __forceinline__ void cpa16(uint32_t dst, const void* src) {
    asm volatile("cp.async.ca.shared.global [%0], [%1], 16;"
                 :: "r"(dst), "l"(src) : "memory");
}
#define CP_COMMIT() asm volatile("cp.async.commit_group;" ::: "memory")
#define CP_WAIT(n)  asm volatile("cp.async.wait_group %0;" :: "n"(n) : "memory")

// Split 8 fp32 into fp16 hi (16 B) and fp16 lo (16 B).
static __device__ __forceinline__ void cvt8(
    float4 p, float4 q, uint4& hi, uint4& lo)
{
    __half2 h0 = __floats2half2_rn(p.x, p.y);
    __half2 h1 = __floats2half2_rn(p.z, p.w);
    __half2 h2 = __floats2half2_rn(q.x, q.y);
    __half2 h3 = __floats2half2_rn(q.z, q.w);
    float2 f0 = __half22float2(h0), f1 = __half22float2(h1);
    float2 f2 = __half22float2(h2), f3 = __half22float2(h3);
    __half2 l0 = __floats2half2_rn(p.x - f0.x, p.y - f0.y);
    __half2 l1 = __floats2half2_rn(p.z - f1.x, p.w - f1.y);
    __half2 l2 = __floats2half2_rn(q.x - f2.x, q.y - f2.y);
    __half2 l3 = __floats2half2_rn(q.z - f3.x, q.w - f3.y);
    hi.x = *(uint32_t*)&h0; hi.y = *(uint32_t*)&h1;
    hi.z = *(uint32_t*)&h2; hi.w = *(uint32_t*)&h3;
    lo.x = *(uint32_t*)&l0; lo.y = *(uint32_t*)&l1;
    lo.z = *(uint32_t*)&l2; lo.w = *(uint32_t*)&l3;
}

// Shared top-8 + renormalized softmax writer (ties -> lower index).
static __device__ __forceinline__ void topk_and_write(
    const float* v_in, int row, float* vals, float* inds)
{
    float v[N_EXP];
#pragma unroll
    for (int j = 0; j < N_EXP; j++) v[j] = v_in[j];

    float tv[TOPK]; int ti[TOPK];
#pragma unroll
    for (int it = 0; it < TOPK; it++) {
        float bv = -INFINITY; int bi = 0;
#pragma unroll
        for (int j = 0; j < N_EXP; j++)
            if (v[j] > bv) { bv = v[j]; bi = j; }
        tv[it] = bv; ti[it] = bi;
        v[bi] = -INFINITY;
    }

    const float m = tv[0];
    float e[TOPK], s = 0.0f;
#pragma unroll
    for (int i = 0; i < TOPK; i++) { e[i] = expf(tv[i] - m); s += e[i]; }
    const float inv = 1.0f / s;

    *(float4*)(vals + (size_t)row * TOPK) =
        make_float4(e[0]*inv, e[1]*inv, e[2]*inv, e[3]*inv);
    *(float4*)(vals + (size_t)row * TOPK + 4) =
        make_float4(e[4]*inv, e[5]*inv, e[6]*inv, e[7]*inv);
    *(float4*)(inds + (size_t)row * TOPK) =
        make_float4((float)ti[0], (float)ti[1], (float)ti[2], (float)ti[3]);
    *(float4*)(inds + (size_t)row * TOPK + 4) =
        make_float4((float)ti[4], (float)ti[5], (float)ti[6], (float)ti[7]);
}

// ---------------------------------------------------------------------------
// Fused kernel: HMMA fp16-split GEMM (dual accumulators) + top-8 + renorm
// softmax + IN-CTA serial-fp32 repair of this CTA's marginal rows.
// Single kernel, no global state.
// ---------------------------------------------------------------------------
__global__ void __launch_bounds__(256, 1)
router_fused_kernel(const float* __restrict__ A,   // [T, H]
                    const float* __restrict__ W,   // [E, H]
                    float* __restrict__ logits,    // [T, E]
                    float* __restrict__ vals,      // [T, 8]
                    float* __restrict__ inds)      // [T, 8]
{
    extern __shared__ char smem[];
    const uint32_t sb = smem_u32(smem);
    const int tid  = threadIdx.x;
    const int wid  = tid >> 5;
    const int lane = tid & 31;
    const int blockRow = blockIdx.x * BM;
    const int mrow = wid * 16;

    float acc[8][4];     // hi*hi
    float acc2[8][4];    // hi*lo + lo*hi
#pragma unroll
    for (int t = 0; t < 8; t++)
#pragma unroll
        for (int j = 0; j < 4; j++) { acc[t][j] = 0.0f; acc2[t][j] = 0.0f; }

    const float* Abase = A + (size_t)blockRow * H_DIM;

    const int ldRowA[4] = { (tid + 0*256) >> 3, (tid + 1*256) >> 3,
                            (tid + 2*256) >> 3, (tid + 3*256) >> 3 };
    const int ldG = tid & 7;

    float4 pa[4][2], pw[2][2];

    // ---- prologue: LDG chunk 0, convert+store into buffer 0
#pragma unroll
    for (int t = 0; t < 4; t++) {
        const float* p = Abase + (size_t)ldRowA[t] * H_DIM + ldG * 8;
        pa[t][0] = *(const float4*)p;
        pa[t][1] = *(const float4*)(p + 4);
    }
#pragma unroll
    for (int t = 0; t < 2; t++) {
        int row = (tid + t * 256) >> 3;
        const float* p = W + (size_t)row * H_DIM + ldG * 8;
        pw[t][0] = *(const float4*)p;
        pw[t][1] = *(const float4*)(p + 4);
    }
#pragma unroll
    for (int t = 0; t < 4; t++) {
        uint4 hi, lo;
        cvt8(pa[t][0], pa[t][1], hi, lo);
        int off = ldRowA[t] * 128 + SWG(ldRowA[t], ldG) * 16;
        *(uint4*)(smem + AHI_OFF(0) + off) = hi;
        *(uint4*)(smem + ALO_OFF(0) + off) = lo;
    }
#pragma unroll
    for (int t = 0; t < 2; t++) {
        int row = (tid + t * 256) >> 3;
        uint4 hi, lo;
        cvt8(pw[t][0], pw[t][1], hi, lo);
        int off = row * 128 + SWG(row, ldG) * 16;
        *(uint4*)(smem + BHI_OFF(0) + off) = hi;
        *(uint4*)(smem + BLO_OFF(0) + off) = lo;
    }

    const int lj  = lane >> 3;
    const int lrr = lane & 7;
    const int jr  = (lj & 1) * 8 + lrr;
    const int jg  = lj >> 1;

    for (int c = 0; c < NCHUNK; c++) {
        const int buf = c & 1;

        // ---- issue next chunk's global loads (consumed after MMA)
        if (c + 1 < NCHUNK) {
            const float* Ab = Abase + (c + 1) * KC;
            const float* Wb = W + (c + 1) * KC;
#pragma unroll
            for (int t = 0; t < 4; t++) {
                const float* p = Ab + (size_t)ldRowA[t] * H_DIM + ldG * 8;
                pa[t][0] = *(const float4*)p;
                pa[t][1] = *(const float4*)(p + 4);
            }
#pragma unroll
            for (int t = 0; t < 2; t++) {
                int row = (tid + t * 256) >> 3;
                const float* p = Wb + (size_t)row * H_DIM + ldG * 8;
                pw[t][0] = *(const float4*)p;
                pw[t][1] = *(const float4*)(p + 4);
            }
        }

        __syncthreads();   // all warps' stores into buf are complete

        // ---- MMA over buf: 4 k16-steps
#pragma unroll
        for (int ks = 0; ks < 4; ks++) {
            const int gk = ks * 2;

            uint32_t ah[4], al[4];
            {
                int arow = mrow + jr;
                int ag   = gk + jg;
                uint32_t off = arow * 128 + SWG(arow, ag) * 16;
                ldsm4(ah, sb + AHI_OFF(buf) + off);
                ldsm4(al, sb + ALO_OFF(buf) + off);
            }

            uint32_t bh[8][2], bl[8][2];
#pragma unroll
            for (int p = 0; p < 4; p++) {
                int brow = p * 16 + jr;
                int bg   = gk + jg;
                uint32_t off = brow * 128 + SWG(brow, bg) * 16;
                uint32_t r[4];
                ldsm4(r, sb + BHI_OFF(buf) + off);
                bh[2*p][0] = r[0]; bh[2*p][1] = r[2];
                bh[2*p+1][0] = r[1]; bh[2*p+1][1] = r[3];
                ldsm4(r, sb + BLO_OFF(buf) + off);
                bl[2*p][0] = r[0]; bl[2*p][1] = r[2];
                bl[2*p+1][0] = r[1]; bl[2*p+1][1] = r[3];
            }

#pragma unroll
            for (int t = 0; t < 8; t++) {
                mma16816(acc[t],  ah, bh[t][0], bh[t][1]);   // hi*hi -> acc
                mma16816(acc2[t], ah, bl[t][0], bl[t][1]);   // hi*lo -> acc2
                mma16816(acc2[t], al, bh[t][0], bh[t][1]);   // lo*hi -> acc2
            }
        }

        // ---- convert + store next chunk into the other buffer
        if (c + 1 < NCHUNK) {
            const int nbuf = buf ^ 1;
#pragma unroll
            for (int t = 0; t < 4; t++) {
                uint4 hi, lo;
                cvt8(pa[t][0], pa[t][1], hi, lo);
                int off = ldRowA[t] * 128 + SWG(ldRowA[t], ldG) * 16;
                *(uint4*)(smem + AHI_OFF(nbuf) + off) = hi;
                *(uint4*)(smem + ALO_OFF(nbuf) + off) = lo;
            }
#pragma unroll
            for (int t = 0; t < 2; t++) {
                int row = (tid + t * 256) >> 3;
                uint4 hi, lo;
                cvt8(pw[t][0], pw[t][1], hi, lo);
                int off = row * 128 + SWG(row, ldG) * 16;
                *(uint4*)(smem + BHI_OFF(nbuf) + off) = hi;
                *(uint4*)(smem + BLO_OFF(nbuf) + off) = lo;
            }
        }
    }

    // Fold the small-term accumulator in once.
#pragma unroll
    for (int t = 0; t < 8; t++)
#pragma unroll
        for (int j = 0; j < 4; j++) acc[t][j] += acc2[t][j];

    __syncthreads();   // all warps done with the final MMA buffer

    // ---------------- Epilogue ----------------
    float* rs = (float*)smem;            // float view of dynamic smem
    int*   rlist = (int*)(rs + RP_LIST); // disjoint from lsm region
    int*   rcnt  = (int*)(rs + RP_CNT);
    if (tid == 0) *rcnt = 0;             // MMA bufs no longer live

    float* lsm = (float*)smem;   // [128][68] f32 (34816 B)
    {
        const int group = lane >> 2, tig = lane & 3;
#pragma unroll
        for (int t = 0; t < 8; t++) {
            int col = t * 8 + 2 * tig;
            *(float2*)&lsm[(mrow + group)     * 68 + col] =
                make_float2(acc[t][0], acc[t][1]);
            *(float2*)&lsm[(mrow + group + 8) * 68 + col] =
                make_float2(acc[t][2], acc[t][3]);
        }
    }
    __syncthreads();

    // Coalesced logits store
#pragma unroll
    for (int t = 0; t < 8; t++) {
        int i = tid + t * 256;
        int row = i >> 4, q = i & 15;
        float4 v = *(float4*)&lsm[row * 68 + q * 4];
        *(float4*)&logits[(size_t)(blockRow + row) * N_EXP + q * 4] = v;
    }

    // Top-8 + renorm softmax + marginal-row flag: threads 0..127, one row each
    if (tid < BM) {
        const int row = blockRow + tid;
        float v[N_EXP];
#pragma unroll
        for (int j = 0; j < N_EXP; j++) v[j] = lsm[tid * 68 + j];

        float tv[TOPK + 1]; int ti[TOPK];
#pragma unroll
        for (int it = 0; it < TOPK; it++) {
            float bv = -INFINITY; int bi = 0;
#pragma unroll
            for (int j = 0; j < N_EXP; j++)
                if (v[j] > bv) { bv = v[j]; bi = j; }
            tv[it] = bv; ti[it] = bi;
            v[bi] = -INFINITY;
        }
        {
            float bv = -INFINITY;
#pragma unroll
            for (int j = 0; j < N_EXP; j++) bv = fmaxf(bv, v[j]);
            tv[TOPK] = bv;
        }

        float min_gap = INFINITY;
#pragma unroll
        for (int i = 0; i < TOPK; i++) min_gap = fminf(min_gap, tv[i] - tv[i + 1]);
        if (min_gap < GAP_THR) {
            int idx = atomicAdd(rcnt, 1);   // smem atomic, CTA-local
            rlist[idx] = row;
        }

        const float m = tv[0];
        float e[TOPK], s = 0.0f;
#pragma unroll
        for (int i = 0; i < TOPK; i++) { e[i] = expf(tv[i] - m); s += e[i]; }
        const float inv = 1.0f / s;

        *(float4*)(vals + (size_t)row * TOPK) =
            make_float4(e[0]*inv, e[1]*inv, e[2]*inv, e[3]*inv);
        *(float4*)(vals + (size_t)row * TOPK + 4) =
            make_float4(e[4]*inv, e[5]*inv, e[6]*inv, e[7]*inv);
        *(float4*)(inds + (size_t)row * TOPK) =
            make_float4((float)ti[0], (float)ti[1], (float)ti[2], (float)ti[3]);
        *(float4*)(inds + (size_t)row * TOPK + 4) =
            make_float4((float)ti[4], (float)ti[5], (float)ti[6], (float)ti[7]);
    }
    __syncthreads();

    // ---------------- In-CTA repair of marginal rows ----------------
    const int nflag = *rcnt;
    if (nflag == 0) return;

    float* slog = rs + RP_SLOG;          // [4][64]
    const int e  = tid & 63;             // expert
    const int ri = tid >> 6;             // row slot (0..3)

    // prefetch k-chunk c (64 floats) into buffer b; W from L2 (just streamed)
#define RP_PREFETCH(c, b, base) do {                                         \
        const float* Wc = W + (c) * RP_KC;                                   \
        uint32_t swb = sb + (RP_W + (b) * RP_WBUF) * 4;                      \
        _Pragma("unroll")                                                    \
        for (int j = 0; j < 4; j++) {                                        \
            int i = tid + 256 * j;       /* 64 rows x 16 float4 = 1024 */    \
            int wrow = i >> 4, q = i & 15;                                   \
            cpa16(swb + (wrow * RP_WSTR + q * 4) * 4,                        \
                  Wc + (size_t)wrow * H_DIM + q * 4);                        \
        }                                                                    \
        if (tid < 64) {                  /* 4 rows x 16 float4 */            \
            int rr = tid >> 4, q = tid & 15;                                 \
            int arow = ((base) + rr < nflag) ? rlist[(base) + rr] : 0;       \
            uint32_t sab = sb + (RP_A + (b) * (4 * RP_KC)                    \
                                  + rr * RP_KC + q * 4) * 4;                 \
            cpa16(sab, A + (size_t)arow * H_DIM + (c) * RP_KC + q * 4);      \
        }                                                                    \
        CP_COMMIT();                                                         \
    } while (0)

    for (int base = 0; base < nflag; base += 4) {
        __syncthreads();                 // bufs/slog/rlist reuse safe
        const int myrow = (base + ri < nflag) ? rlist[base + ri] : -1;

        RP_PREFETCH(0, 0, base);
        RP_PREFETCH(1, 1, base);

        float accr = 0.0f;

        for (int c = 0; c < RP_NCH; c++) {
            const int buf = c % 3;
            if (c < RP_NCH - 1) { CP_WAIT(1); }
            else                { CP_WAIT(0); }
            __syncthreads();             // chunk c visible; buf (c+2)%3 free
            if (c + 2 < RP_NCH) RP_PREFETCH(c + 2, (c + 2) % 3, base);

            const float* swr = rs + RP_W + buf * RP_WBUF + e * RP_WSTR;
            const float* sa  = rs + RP_A + buf * (4 * RP_KC) + ri * RP_KC;

#pragma unroll
            for (int k4 = 0; k4 < RP_KC / 4; k4++) {
                float4 w4 = *(const float4*)(swr + k4 * 4);
                float4 a4 = *(const float4*)(sa + k4 * 4);
                accr = fmaf(a4.x, w4.x, accr);
                accr = fmaf(a4.y, w4.y, accr);
                accr = fmaf(a4.z, w4.z, accr);
                accr = fmaf(a4.w, w4.w, accr);
            }
        }

        slog[ri * N_EXP + e] = accr;
        if (myrow >= 0) logits[(size_t)myrow * N_EXP + e] = accr;
        __syncthreads();

        if (e == 0 && myrow >= 0)
            topk_and_write(slog + ri * N_EXP, myrow, vals, inds);
    }
#undef RP_PREFETCH
}

// ---------------------------------------------------------------------------
// Launch — single kernel
// ---------------------------------------------------------------------------
extern "C" void kernel_launch(void* const* d_in, const int* in_sizes, int n_in,
                              void* d_out, int out_size)
{
    const float* hidden = (const float*)d_in[0];   // [16384, 2048]
    const float* weight = (const float*)d_in[1];   // [64, 2048]
    float* out = (float*)d_out;

    float* logits = out;                                 // 16384*64
    float* vals   = out + (size_t)T_TOKENS * N_EXP;      // 16384*8
    float* inds   = vals + (size_t)T_TOKENS * TOPK;      // 16384*8

    cudaFuncSetAttribute(router_fused_kernel,
                         cudaFuncAttributeMaxDynamicSharedMemorySize, SMEM_TOTAL);
    router_fused_kernel<<<T_TOKENS / BM, 256, SMEM_TOTAL>>>(
        hidden, weight, logits, vals, inds);
}